// round 1
// baseline (speedup 1.0000x reference)
#include <cuda_runtime.h>

// ---------------------------------------------------------------------------
// enc_mtan_classif — collapsed computation:
//   A[b,c]  = masked mean of x over t   (softmax quirk makes attention = this)
//   G[b,n]  = A @ Wo^T + bo
//   gi[b,j] = G @ W_ih^T + b_ih        (GRU input identical at every step)
//   GRU 128 steps (per-batch-row independent -> 1 row per CTA/SM)
//   out = MLP(hT)
// ---------------------------------------------------------------------------

__device__ float g_WihT[128 * 384];  // [n][j] = W_ih[j,n]
__device__ float g_WhhT[128 * 384];  // [k][j] = W_hh[j,k]
__device__ float g_W1T[128 * 300];   // [k][i] = W1[i,k]
__device__ float g_W2T[300 * 300];   // [k][i] = W2[i,k]

__global__ void transpose_kernel(const float* __restrict__ W_ih,
                                 const float* __restrict__ W_hh,
                                 const float* __restrict__ W1,
                                 const float* __restrict__ W2) {
    int idx = blockIdx.x * blockDim.x + threadIdx.x;
    if (idx < 384 * 128) {
        int j = idx >> 7, k = idx & 127;
        g_WihT[k * 384 + j] = W_ih[idx];
        g_WhhT[k * 384 + j] = W_hh[idx];
        return;
    }
    int i1 = idx - 384 * 128;
    if (i1 >= 0 && i1 < 300 * 128) {
        int i = i1 >> 7, k = i1 & 127;
        g_W1T[k * 300 + i] = W1[i1];
        return;
    }
    int i2 = idx - (384 * 128 + 300 * 128);
    if (i2 >= 0 && i2 < 300 * 300) {
        int i = i2 / 300, k = i2 - i * 300;
        g_W2T[k * 300 + i] = W2[i2];
    }
}

__device__ __forceinline__ void fma2(unsigned long long& d,
                                     unsigned long long a,
                                     unsigned long long b) {
    asm("fma.rn.f32x2 %0, %1, %2, %0;" : "+l"(d) : "l"(a), "l"(b));
}
__device__ __forceinline__ unsigned long long pack2(float lo, float hi) {
    unsigned long long r;
    asm("mov.b64 %0, {%1, %2};" : "=l"(r) : "f"(lo), "f"(hi));
    return r;
}
__device__ __forceinline__ float2 unpack2(unsigned long long v) {
    float2 f;
    asm("mov.b64 {%0, %1}, %2;" : "=f"(f.x), "=f"(f.y) : "l"(v));
    return f;
}
__device__ __forceinline__ float sigmoidf_(float x) {
    return 1.0f / (1.0f + __expf(-x));
}
__device__ __forceinline__ float tanhf_(float x) {
    float e = __expf(-2.0f * fabsf(x));
    float t = (1.0f - e) / (1.0f + e);
    return copysignf(t, x);
}

__global__ __launch_bounds__(384, 1) void mtan_kernel(
    const float* __restrict__ x,
    const float* __restrict__ Wo, const float* __restrict__ bo,
    const float* __restrict__ b_ih, const float* __restrict__ b_hh,
    const float* __restrict__ b1, const float* __restrict__ b2,
    const float* __restrict__ W3, const float* __restrict__ b3,
    float* __restrict__ out) {
    __shared__ __align__(16) float x_s[128 * 32];
    __shared__ float red[3][12][32];
    __shared__ float A_s[32];
    __shared__ __align__(16) float G_s[128];
    __shared__ __align__(16) float h_s[128];
    __shared__ float d_s[384];
    __shared__ float gin_s[128];
    __shared__ float y1_s[300];
    __shared__ float y2_s[300];

    const int tid = threadIdx.x;
    const int b = blockIdx.x;

    // ---- load x[b] (16KB) into smem, coalesced float4 ----
    {
        const float4* xg = reinterpret_cast<const float4*>(x + b * 4096);
        float4* xs4 = reinterpret_cast<float4*>(x_s);
        for (int i = tid; i < 1024; i += 384) xs4[i] = xg[i];
    }
    __syncthreads();

    // ---- masked mean A[c] (c<16: sum(m*v)/sum(m); c>=16: same formula -> 1) ----
    {
        int c = tid & 31, seg = tid >> 5;  // 12 segments
        float num = 0.f, den = 0.f, tot = 0.f;
        for (int t = seg; t < 128; t += 12) {
            float v = x_s[t * 32 + c];
            float m = x_s[t * 32 + 16 + (c & 15)];
            num = fmaf(m, v, num);
            den += m;
            tot += v;
        }
        red[0][seg][c] = num;
        red[1][seg][c] = den;
        red[2][seg][c] = tot;
    }
    __syncthreads();
    if (tid < 32) {
        float n = 0.f, d = 0.f, t = 0.f;
#pragma unroll
        for (int s = 0; s < 12; ++s) {
            n += red[0][s][tid];
            d += red[1][s][tid];
            t += red[2][s][tid];
        }
        A_s[tid] = (d > 0.5f) ? (n / d) : (t * (1.0f / 128.0f));
    }
    __syncthreads();

    // ---- G[n] = A @ Wo^T + bo ----
    if (tid < 128) {
        float acc = bo[tid];
        const float* wrow = Wo + tid * 32;
#pragma unroll
        for (int c = 0; c < 32; ++c) acc = fmaf(A_s[c], wrow[c], acc);
        G_s[tid] = acc;
    }
    __syncthreads();

    // ---- gi[j] = G @ W_ih^T + b_ih  (coalesced via transposed W_ih) ----
    float e_j;        // precomputed constant added to the recurrent dot
    float gin = 0.f;  // inn + b_in, for update threads (tid<128)
    {
        float a0 = b_ih[tid], a1 = 0.f, a2 = 0.f, a3 = 0.f;
#pragma unroll 4
        for (int n = 0; n < 128; n += 4) {
            a0 = fmaf(G_s[n + 0], g_WihT[(n + 0) * 384 + tid], a0);
            a1 = fmaf(G_s[n + 1], g_WihT[(n + 1) * 384 + tid], a1);
            a2 = fmaf(G_s[n + 2], g_WihT[(n + 2) * 384 + tid], a2);
            a3 = fmaf(G_s[n + 3], g_WihT[(n + 3) * 384 + tid], a3);
        }
        float gi = ((a0 + a1) + (a2 + a3));
        if (tid >= 256) {
            gin_s[tid - 256] = gi;   // pure inn + b_in
            e_j = b_hh[tid];         // hn gets only b_hh folded in
        } else {
            e_j = gi + b_hh[tid];    // r,z gates: fold everything
        }
    }
    __syncthreads();
    if (tid < 128) gin = gin_s[tid];

    // ---- W_hh row -> registers (coalesced via transposed layout), f32x2 packed ----
    unsigned long long wr[64];
#pragma unroll
    for (int m = 0; m < 64; ++m) {
        float lo = g_WhhT[(2 * m + 0) * 384 + tid];
        float hi = g_WhhT[(2 * m + 1) * 384 + tid];
        wr[m] = pack2(lo, hi);
    }

    // ---- GRU recurrence, 128 steps ----
    if (tid < 128) h_s[tid] = 0.f;
    float hj = 0.f;
    __syncthreads();

    const ulonglong2* hs2 = reinterpret_cast<const ulonglong2*>(h_s);

#pragma unroll 1
    for (int step = 0; step < 128; ++step) {
        unsigned long long a0 = 0ULL, a1 = 0ULL, a2 = 0ULL, a3 = 0ULL;
#pragma unroll
        for (int i = 0; i < 32; i += 2) {
            ulonglong2 hv0 = hs2[i];
            ulonglong2 hv1 = hs2[i + 1];
            fma2(a0, wr[2 * i + 0], hv0.x);
            fma2(a1, wr[2 * i + 1], hv0.y);
            fma2(a2, wr[2 * i + 2], hv1.x);
            fma2(a3, wr[2 * i + 3], hv1.y);
        }
        float2 f0 = unpack2(a0), f1 = unpack2(a1);
        float2 f2 = unpack2(a2), f3 = unpack2(a3);
        float dot =
            (((f0.x + f0.y) + (f1.x + f1.y)) + ((f2.x + f2.y) + (f3.x + f3.y))) +
            e_j;
        // apply sigmoid in the producing thread (parallel, off the critical tail)
        d_s[tid] = (tid < 256) ? sigmoidf_(dot) : dot;
        __syncthreads();
        if (tid < 128) {
            float r = d_s[tid];
            float z = d_s[tid + 128];
            float n = tanhf_(fmaf(r, d_s[tid + 256], gin));
            hj = n + z * (hj - n);
            h_s[tid] = hj;
        }
        __syncthreads();
    }

    // ---- MLP head: 128 -> 300 -> 300 -> 2 (h final lives in h_s) ----
    if (tid < 300) {
        float a0 = b1[tid], a1 = 0.f, a2 = 0.f, a3 = 0.f;
#pragma unroll 4
        for (int k = 0; k < 128; k += 4) {
            a0 = fmaf(h_s[k + 0], g_W1T[(k + 0) * 300 + tid], a0);
            a1 = fmaf(h_s[k + 1], g_W1T[(k + 1) * 300 + tid], a1);
            a2 = fmaf(h_s[k + 2], g_W1T[(k + 2) * 300 + tid], a2);
            a3 = fmaf(h_s[k + 3], g_W1T[(k + 3) * 300 + tid], a3);
        }
        y1_s[tid] = fmaxf((a0 + a1) + (a2 + a3), 0.f);
    }
    __syncthreads();
    if (tid < 300) {
        float a0 = b2[tid], a1 = 0.f, a2 = 0.f, a3 = 0.f;
#pragma unroll 4
        for (int k = 0; k < 300; k += 4) {
            a0 = fmaf(y1_s[k + 0], g_W2T[(k + 0) * 300 + tid], a0);
            a1 = fmaf(y1_s[k + 1], g_W2T[(k + 1) * 300 + tid], a1);
            a2 = fmaf(y1_s[k + 2], g_W2T[(k + 2) * 300 + tid], a2);
            a3 = fmaf(y1_s[k + 3], g_W2T[(k + 3) * 300 + tid], a3);
        }
        y2_s[tid] = fmaxf((a0 + a1) + (a2 + a3), 0.f);
    }
    __syncthreads();
    {
        int w = tid >> 5, l = tid & 31;
        if (w < 2) {
            float a = 0.f;
            for (int k = l; k < 300; k += 32)
                a = fmaf(y2_s[k], W3[w * 300 + k], a);
#pragma unroll
            for (int off = 16; off; off >>= 1)
                a += __shfl_down_sync(0xffffffffu, a, off);
            if (l == 0) out[b * 2 + w] = a + b3[w];
        }
    }
}

extern "C" void kernel_launch(void* const* d_in, const int* in_sizes, int n_in,
                              void* d_out, int out_size) {
    (void)in_sizes;
    (void)n_in;
    (void)out_size;
    const float* x = (const float*)d_in[0];
    // d_in[1..9] (query_p, time-embedding + Q/K proj weights) are provably
    // dead: the broadcast quirk makes softmax uniform over valid mask slots.
    const float* Wo = (const float*)d_in[10];
    const float* bo = (const float*)d_in[11];
    const float* W_ih = (const float*)d_in[12];
    const float* W_hh = (const float*)d_in[13];
    const float* b_ih = (const float*)d_in[14];
    const float* b_hh = (const float*)d_in[15];
    const float* W1 = (const float*)d_in[16];
    const float* b1 = (const float*)d_in[17];
    const float* W2 = (const float*)d_in[18];
    const float* b2 = (const float*)d_in[19];
    const float* W3 = (const float*)d_in[20];
    const float* b3 = (const float*)d_in[21];
    float* out = (float*)d_out;

    const int total = 384 * 128 + 300 * 128 + 300 * 300;
    transpose_kernel<<<(total + 255) / 256, 256>>>(W_ih, W_hh, W1, W2);
    mtan_kernel<<<128, 384>>>(x, Wo, bo, b_ih, b_hh, b1, b2, W3, b3, out);
}